// round 3
// baseline (speedup 1.0000x reference)
#include <cuda_runtime.h>
#include <math.h>

#define N_POINTS 128
#define STEPS    50
#define N_EVENTS 10000
#define DT       2.0f
#define SQRT_PI_F 1.7724539f

#define N_PAIRS    ((N_POINTS * (N_POINTS - 1)) / 2)      // 8128
#define PAIR_TOTAL (N_PAIRS * STEPS)                      // 406400
#define TOTAL_WORK (PAIR_TOTAL + N_EVENTS)                // 416400

#define BLOCKS  148
#define THREADS 512
#define NTHREADS_ALL (BLOCKS * THREADS)                   // 75776
#define CHUNK ((TOTAL_WORK + NTHREADS_ALL - 1) / NTHREADS_ALL)   // 6

// smem layout (floats): Z[256*50] | ts[51] | validf[50] | pad | red[16 doubles]
#define SM_Z     0
#define SM_TS    (256 * STEPS)            // 12800
#define SM_VALID (SM_TS + STEPS + 1)      // 12851
#define SM_REDF  (SM_VALID + STEPS + 3)   // 12904 (8-byte aligned)
#define SMEM_FLOATS (SM_REDF + 32)        // + 16 doubles
#define SMEM_BYTES  (SMEM_FLOATS * 4)     // 51744

__device__ double       g_acc   = 0.0;
__device__ unsigned int g_count = 0;

__device__ __forceinline__ int tri_base(int i) {          // # pairs before row i
    return i * (N_POINTS - 1) - (i * (i - 1)) / 2;
}

// Abramowitz-Stegun 7.1.26: |err| < 1.5e-7
__device__ __forceinline__ float fast_erff(float x) {
    float ax = fabsf(x);
    float t  = __fdividef(1.0f, fmaf(0.3275911f, ax, 1.0f));
    float poly = t * fmaf(t, fmaf(t, fmaf(t, fmaf(t, 1.061405429f,
                    -1.453152027f), 1.421413741f), -0.284496736f), 0.254829592f);
    float r = 1.0f - poly * __expf(-ax * ax);
    return copysignf(r, x);
}

__global__ void __launch_bounds__(THREADS)
fused_kernel(const float* __restrict__ data,
             const float* __restrict__ beta,
             const float* __restrict__ z0,
             const float* __restrict__ v0,
             float* __restrict__ out) {
    extern __shared__ float sm[];
    float*  sZ  = sm + SM_Z;       // [row = point*2 + dim][s], 50 per row
    float*  sTs = sm + SM_TS;      // ts[0..49], slot 50 = times[M-1]
    float*  sVl = sm + SM_VALID;   // valid mask as float
    double* sRd = (double*)(sm + SM_REDF);

    const int   tid   = threadIdx.x;
    const float denom = DT + DT * 0.001f;                 // 2.002f (matches ref rounding)
    const float tlast = __ldg(&data[(N_EVENTS - 1) * 3 + 2]);

    // ---- prep phase (redundant per block, all in shared) ----
    if (tid <= STEPS) {
        sTs[tid] = tlast;                                 // empty segment -> times[-1]
        if (tid < STEPS) sVl[tid] = 0.0f;
    }
    __syncthreads();

    // Z cumsum: one row per thread (256 rows of 50)
    if (tid < 2 * N_POINTS) {
        float z = __ldg(&z0[tid]);
        const float* vr = v0 + tid * STEPS;
        float* Zr = sZ + tid * STEPS;
        Zr[0] = z;                                        // Z_steps[0] = z0
        float cum = 0.0f;
        #pragma unroll
        for (int s = 1; s < STEPS; ++s) {
            cum += z + vr[s - 1] * DT;                    // Z_steps[s]
            Zr[s] = cum;
        }
    }
    // segment boundary scan over sorted times (parallel, coalesced)
    for (int m = tid; m < N_EVENTS; m += THREADS) {
        float t   = data[m * 3 + 2];
        int   idx = (int)floorf(t / denom);
        int newseg;
        if (m == 0) newseg = 1;
        else {
            float tp = data[m * 3 - 1];                   // times[m-1]
            newseg = ((int)floorf(tp / denom)) != idx;
        }
        if (newseg) { sTs[idx] = t; sVl[idx] = 1.0f; }
    }
    __syncthreads();

    // ---- main phase: contiguous chunk of terms per thread ----
    const float b0 = __ldg(&beta[0]);
    double local = 0.0;

    int t0 = (blockIdx.x * THREADS + tid) * CHUNK;
    if (t0 < TOTAL_WORK) {
        int i = 0, j = 1, s = 0;
        if (t0 < PAIR_TOTAL) {                            // triangular decode with fixup
            int p = t0 / STEPS;
            s = t0 - p * STEPS;
            float disc = (float)(255 * 255 - 8 * p);
            i = (int)((255.0f - sqrtf(disc)) * 0.5f);
            i = min(max(i, 0), N_POINTS - 2);
            while (i < N_POINTS - 2 && tri_base(i + 1) <= p) ++i;
            while (i > 0 && tri_base(i) > p) --i;
            j = i + 1 + (p - tri_base(i));
        }

        #pragma unroll
        for (int k = 0; k < CHUNK; ++k) {
            int q = t0 + k;
            if (q >= TOTAL_WORK) break;
            if (q < PAIR_TOTAL) {
                int oi = i * 100 + s, oj = j * 100 + s;
                float dzx = sZ[oi]      - sZ[oj];
                float dzy = sZ[oi + 50] - sZ[oj + 50];
                float dvx = __ldg(&v0[oi])      - __ldg(&v0[oj]);
                float dvy = __ldg(&v0[oi + 50]) - __ldg(&v0[oj + 50]);

                float a = fmaxf(dvx * dvx + dvy * dvy, 1e-10f);
                float b = 2.0f * (dzx * dvx + dzy * dvy);
                float c = dzx * dzx + dzy * dzy;
                float rsa    = rsqrtf(a);
                float sa     = a * rsa;
                float inv2sa = 0.5f * rsa;
                float shift  = b * inv2sa;
                float pref   = SQRT_PI_F * inv2sa * __expf(b0 - c + shift * shift);
                float ts = sTs[s], tf = sTs[s + 1];
                float integ = pref * (fast_erff(fmaf(sa, tf, shift))
                                    - fast_erff(fmaf(sa, ts, shift)));
                local -= (double)(integ * sVl[s]);        // result = events - non_events
                if (++s == STEPS) {                       // advance (i,j,s)
                    s = 0;
                    if (++j == N_POINTS) { ++i; j = i + 1; }
                }
            } else {
                int e = q - PAIR_TOTAL;
                float si = data[e * 3], dj = data[e * 3 + 1], t = data[e * 3 + 2];
                int ii = (int)si, jj = (int)dj;
                float stepf = floorf(t / denom);
                int   id    = (int)stepf;
                float delta = t - stepf * DT;
                int oi = ii * 100 + id, oj = jj * 100 + id;
                float dx = (sZ[oi]      + __ldg(&v0[oi])      * delta)
                         - (sZ[oj]      + __ldg(&v0[oj])      * delta);
                float dy = (sZ[oi + 50] + __ldg(&v0[oi + 50]) * delta)
                         - (sZ[oj + 50] + __ldg(&v0[oj + 50]) * delta);
                local += (double)(b0 - (dx * dx + dy * dy));
            }
        }
    }

    // ---- reduction: warp shuffle -> smem -> warp0 -> global atomic ----
    double v = local;
    #pragma unroll
    for (int off = 16; off > 0; off >>= 1)
        v += __shfl_down_sync(0xffffffffu, v, off);
    int warp = tid >> 5, lane = tid & 31;
    if (lane == 0) sRd[warp] = v;
    __syncthreads();
    if (warp == 0) {
        v = (lane < THREADS / 32) ? sRd[lane] : 0.0;
        #pragma unroll
        for (int off = 8; off > 0; off >>= 1)
            v += __shfl_down_sync(0xffffffffu, v, off);
        if (lane == 0) {
            atomicAdd(&g_acc, v);
            __threadfence();
            unsigned int old = atomicAdd(&g_count, 1u);
            if (old == gridDim.x - 1) {
                double total = atomicAdd(&g_acc, 0.0);
                out[0] = (float)total;
                g_acc   = 0.0;                            // reset for next graph replay
                g_count = 0u;
            }
        }
    }
}

// Inputs (metadata order): data[30000], t0[1], tn[1], beta[1], z0[256], v0[12800]
extern "C" void kernel_launch(void* const* d_in, const int* in_sizes, int n_in,
                              void* d_out, int out_size) {
    const float* data = (const float*)d_in[0];
    const float* beta = (const float*)d_in[3];
    const float* z0   = (const float*)d_in[4];
    const float* v0   = (const float*)d_in[5];
    float* out = (float*)d_out;

    (void)cudaFuncSetAttribute(fused_kernel,
                               cudaFuncAttributeMaxDynamicSharedMemorySize,
                               SMEM_BYTES);
    fused_kernel<<<BLOCKS, THREADS, SMEM_BYTES>>>(data, beta, z0, v0, out);
}

// round 4
// speedup vs baseline: 1.2189x; 1.2189x over previous
#include <cuda_runtime.h>
#include <math.h>

#define N_POINTS 128
#define STEPS    50
#define N_EVENTS 10000
#define DT       2.0f
#define SQRT_PI_F 1.7724539f

#define N_PAIRS    ((N_POINTS * (N_POINTS - 1)) / 2)      // 8128
#define PAIR_TOTAL (N_PAIRS * STEPS)                      // 406400
#define TOTAL_WORK (PAIR_TOTAL + N_EVENTS)                // 416400

#define MAIN_BLOCKS  592
#define MAIN_THREADS 256
#define CHUNK 3                                           // 592*256*3 = 454656 >= TOTAL_WORK

// ---- device scratch (allocation-free contract) ----
__device__ float g_Z[2 * N_POINTS * STEPS];               // [row = point*2+dim][s]
__device__ float g_ts[STEPS + 1];                         // ts[s]; slot 50 = times[M-1]
__device__ float g_vl[STEPS];                             // valid mask (0/1)
__device__ double       g_acc   = 0.0;
__device__ unsigned int g_count = 0;

__device__ __forceinline__ int tri_base(int i) {          // # pairs before row i
    return i * (N_POINTS - 1) - (i * (i - 1)) / 2;
}

// Abramowitz-Stegun 7.1.26: |err| < 1.5e-7
__device__ __forceinline__ float fast_erff(float x) {
    float ax = fabsf(x);
    float t  = __fdividef(1.0f, fmaf(0.3275911f, ax, 1.0f));
    float poly = t * fmaf(t, fmaf(t, fmaf(t, fmaf(t, 1.061405429f,
                    -1.453152027f), 1.421413741f), -0.284496736f), 0.254829592f);
    float r = 1.0f - poly * __expf(-ax * ax);
    return copysignf(r, x);
}

// ---------------------------------------------------------------------------
// Kernel A: 1 block, 512 threads. Z cumsum + parallel segment-boundary scan.
// ---------------------------------------------------------------------------
__global__ void __launch_bounds__(512)
prep_kernel(const float* __restrict__ data,
            const float* __restrict__ z0,
            const float* __restrict__ v0) {
    __shared__ float sTs[STEPS + 1];
    __shared__ float sVl[STEPS];
    const int   tid   = threadIdx.x;
    const float denom = DT + DT * 0.001f;                 // 2.002f, matches ref rounding
    const float tlast = __ldg(&data[(N_EVENTS - 1) * 3 + 2]);

    if (tid <= STEPS) {
        sTs[tid] = tlast;                                 // empty segment -> times[M-1]
        if (tid < STEPS) sVl[tid] = 0.0f;
    }
    __syncthreads();

    // Z cumsum: one row per thread (256 rows of 50), straight to global
    if (tid < 2 * N_POINTS) {
        float z = __ldg(&z0[tid]);
        const float* vr = v0 + tid * STEPS;
        float* Zr = g_Z + tid * STEPS;
        Zr[0] = z;
        float cum = 0.0f;
        #pragma unroll
        for (int s = 1; s < STEPS; ++s) {
            cum += z + vr[s - 1] * DT;                    // Z_steps[s]
            Zr[s] = cum;
        }
    }
    // boundary scan over sorted event times (independent loads -> MLP-hidden)
    for (int m = tid; m < N_EVENTS; m += 512) {
        float t   = data[m * 3 + 2];
        int   idx = (int)floorf(t / denom);
        int newseg = (m == 0) ||
                     (((int)floorf(data[m * 3 - 1] / denom)) != idx);
        if (newseg) { sTs[idx] = t; sVl[idx] = 1.0f; }
    }
    __syncthreads();
    if (tid <= STEPS) {
        g_ts[tid] = sTs[tid];
        if (tid < STEPS) g_vl[tid] = sVl[tid];
    }
}

// ---------------------------------------------------------------------------
// Kernel B: 592x256. Triangle-only terms + events; fast math + underflow skip.
// ---------------------------------------------------------------------------
__global__ void __launch_bounds__(MAIN_THREADS)
main_kernel(const float* __restrict__ data,
            const float* __restrict__ beta,
            const float* __restrict__ v0,
            float* __restrict__ out) {
    const int   tid   = threadIdx.x;
    const float denom = DT + DT * 0.001f;
    const float b0    = __ldg(&beta[0]);
    double local = 0.0;

    int t0 = (blockIdx.x * MAIN_THREADS + tid) * CHUNK;
    if (t0 < TOTAL_WORK) {
        int i = 0, j = 1, s = 0;
        if (t0 < PAIR_TOTAL) {                            // triangular decode + fixup
            int p = t0 / STEPS;
            s = t0 - p * STEPS;
            float disc = (float)(255 * 255 - 8 * p);
            i = (int)((255.0f - sqrtf(disc)) * 0.5f);
            i = min(max(i, 0), N_POINTS - 2);
            while (i < N_POINTS - 2 && tri_base(i + 1) <= p) ++i;
            while (i > 0 && tri_base(i) > p) --i;
            j = i + 1 + (p - tri_base(i));
        }

        #pragma unroll
        for (int k = 0; k < CHUNK; ++k) {
            int q = t0 + k;
            if (q >= TOTAL_WORK) break;
            if (q < PAIR_TOTAL) {
                int oi = i * 100 + s, oj = j * 100 + s;
                float dzx = __ldg(&g_Z[oi])      - __ldg(&g_Z[oj]);
                float dzy = __ldg(&g_Z[oi + 50]) - __ldg(&g_Z[oj + 50]);
                float dvx = __ldg(&v0[oi])       - __ldg(&v0[oj]);
                float dvy = __ldg(&v0[oi + 50])  - __ldg(&v0[oj + 50]);

                float a = fmaxf(dvx * dvx + dvy * dvy, 1e-10f);
                float b = 2.0f * (dzx * dvx + dzy * dvy);
                float c = dzx * dzx + dzy * dzy;
                float rsa    = rsqrtf(a);
                float inv2sa = 0.5f * rsa;
                float shift  = b * inv2sa;
                float arg    = b0 - c + shift * shift;
                if (arg > -30.0f) {                       // exp underflow early-out
                    float sa   = a * rsa;
                    float pref = SQRT_PI_F * inv2sa * __expf(arg);
                    float ts = __ldg(&g_ts[s]), tf = __ldg(&g_ts[s + 1]);
                    float integ = pref * (fast_erff(fmaf(sa, tf, shift))
                                        - fast_erff(fmaf(sa, ts, shift)));
                    local -= (double)(integ * __ldg(&g_vl[s]));
                }
                if (++s == STEPS) {                       // advance (i,j,s)
                    s = 0;
                    if (++j == N_POINTS) { ++i; j = i + 1; }
                }
            } else {
                int e = q - PAIR_TOTAL;
                float si = data[e * 3], dj = data[e * 3 + 1], t = data[e * 3 + 2];
                int ii = (int)si, jj = (int)dj;
                float stepf = floorf(t / denom);
                int   id    = (int)stepf;
                float delta = t - stepf * DT;
                int oi = ii * 100 + id, oj = jj * 100 + id;
                float dx = (__ldg(&g_Z[oi])      + __ldg(&v0[oi])      * delta)
                         - (__ldg(&g_Z[oj])      + __ldg(&v0[oj])      * delta);
                float dy = (__ldg(&g_Z[oi + 50]) + __ldg(&v0[oi + 50]) * delta)
                         - (__ldg(&g_Z[oj + 50]) + __ldg(&v0[oj + 50]) * delta);
                local += (double)(b0 - (dx * dx + dy * dy));
            }
        }
    }

    // ---- reduction: warp shuffle -> smem -> warp0 -> global atomic ----
    __shared__ double sRd[MAIN_THREADS / 32];
    double v = local;
    #pragma unroll
    for (int off = 16; off > 0; off >>= 1)
        v += __shfl_down_sync(0xffffffffu, v, off);
    int warp = tid >> 5, lane = tid & 31;
    if (lane == 0) sRd[warp] = v;
    __syncthreads();
    if (warp == 0) {
        v = (lane < MAIN_THREADS / 32) ? sRd[lane] : 0.0;
        #pragma unroll
        for (int off = 4; off > 0; off >>= 1)
            v += __shfl_down_sync(0xffffffffu, v, off);
        if (lane == 0) {
            atomicAdd(&g_acc, v);
            __threadfence();
            unsigned int old = atomicAdd(&g_count, 1u);
            if (old == gridDim.x - 1) {
                double total = atomicAdd(&g_acc, 0.0);
                out[0] = (float)total;
                g_acc   = 0.0;                            // reset for next graph replay
                g_count = 0u;
            }
        }
    }
}

// Inputs (metadata order): data[30000], t0[1], tn[1], beta[1], z0[256], v0[12800]
extern "C" void kernel_launch(void* const* d_in, const int* in_sizes, int n_in,
                              void* d_out, int out_size) {
    const float* data = (const float*)d_in[0];
    const float* beta = (const float*)d_in[3];
    const float* z0   = (const float*)d_in[4];
    const float* v0   = (const float*)d_in[5];
    float* out = (float*)d_out;

    prep_kernel<<<1, 512>>>(data, z0, v0);
    main_kernel<<<MAIN_BLOCKS, MAIN_THREADS>>>(data, beta, v0, out);
}